// round 11
// baseline (speedup 1.0000x reference)
#include <cuda_runtime.h>
#include <cuda_bf16.h>
#include <cstdint>
#include <cstddef>
#include <math.h>

#define T_  512
#define B_  64
#define I_  1024
#define H_  1024
#define G4  4096
#define M_  (T_ * B_)   // 32768
#define NBLK 128
#define NTHR 256

// ---------------------------------------------------------------------------
// Scratch (__device__ globals: allocation-free, harness-legal)
// ---------------------------------------------------------------------------
__device__ float g_xpre[(size_t)M_ * G4];            // [T*B, 4H] pre-activations
__device__ __nv_bfloat16 g_hhi[2][B_ * H_];          // h high bf16 (ping-pong)
__device__ __nv_bfloat16 g_hlo[2][B_ * H_];          // h low  bf16 (ping-pong)
__device__ __nv_bfloat16 g_xhi[(size_t)M_ * I_];     // input hi bf16
__device__ __nv_bfloat16 g_xlo[(size_t)M_ * I_];     // input lo bf16
__device__ __nv_bfloat16 g_whi[(size_t)G4 * I_];     // W_ih hi bf16
__device__ __nv_bfloat16 g_wlo[(size_t)G4 * I_];     // W_ih lo bf16
__device__ unsigned g_gen;                           // barrier generation
__device__ unsigned g_root;                          // tree-barrier root
__device__ unsigned g_grp[8 * 32];                   // 8 group counters, 128B apart

__device__ __forceinline__ unsigned ld_acq(unsigned* p) {
    unsigned v;
    asm volatile("ld.acquire.gpu.u32 %0, [%1];" : "=r"(v) : "l"(p) : "memory");
    return v;
}
__device__ __forceinline__ unsigned atom_add_acqrel(unsigned* p) {
    unsigned v;
    asm volatile("atom.acq_rel.gpu.global.add.u32 %0, [%1], 1;"
                 : "=r"(v) : "l"(p) : "memory");
    return v;
}
__device__ __forceinline__ void atom_add_release(unsigned* p) {
    unsigned v;
    asm volatile("atom.release.gpu.global.add.u32 %0, [%1], 1;"
                 : "=r"(v) : "l"(p) : "memory");
}

// ---------------------------------------------------------------------------
// warp-MMA helpers (base-target PTX: sm_80+, compiles for sm_103)
// ---------------------------------------------------------------------------
__device__ __forceinline__ uint32_t smem_u32(const void* p) {
    uint32_t a;
    asm("{ .reg .u64 t; cvta.to.shared.u64 t, %1; cvt.u32.u64 %0, t; }"
        : "=r"(a) : "l"(p));
    return a;
}
__device__ __forceinline__ void ldsm_x4(unsigned* r, uint32_t addr) {
    asm volatile("ldmatrix.sync.aligned.m8n8.x4.shared.b16 {%0,%1,%2,%3}, [%4];"
                 : "=r"(r[0]), "=r"(r[1]), "=r"(r[2]), "=r"(r[3]) : "r"(addr));
}
__device__ __forceinline__ void ldsm_x2(unsigned* r, uint32_t addr) {
    asm volatile("ldmatrix.sync.aligned.m8n8.x2.shared.b16 {%0,%1}, [%2];"
                 : "=r"(r[0]), "=r"(r[1]) : "r"(addr));
}
__device__ __forceinline__ void mma16816(float* c, const unsigned* a,
                                         const unsigned* b) {
    asm volatile("mma.sync.aligned.m16n8k16.row.col.f32.bf16.bf16.f32 "
                 "{%0,%1,%2,%3}, {%4,%5,%6,%7}, {%8,%9}, {%0,%1,%2,%3};"
                 : "+f"(c[0]), "+f"(c[1]), "+f"(c[2]), "+f"(c[3])
                 : "r"(a[0]), "r"(a[1]), "r"(a[2]), "r"(a[3]),
                   "r"(b[0]), "r"(b[1]));
}
__device__ __forceinline__ void cp_async16(uint32_t daddr, const void* src) {
    asm volatile("cp.async.cg.shared.global [%0], [%1], 16;"
                 :: "r"(daddr), "l"(__cvta_generic_to_global(src)));
}
__device__ __forceinline__ void cp_commit() {
    asm volatile("cp.async.commit_group;");
}
template <int N>
__device__ __forceinline__ void cp_wait() {
    asm volatile("cp.async.wait_group %0;" :: "n"(N));
}

// ---------------------------------------------------------------------------
__global__ void reset_barrier() {
    int i = threadIdx.x;
    if (i < 8 * 32) g_grp[i] = 0;
    if (i == 0) { g_gen = 0; g_root = 0; }
}

__global__ void init_state(const float* __restrict__ h0) {
    int i = blockIdx.x * blockDim.x + threadIdx.x;
    if (i < B_ * H_) {
        float x = h0[i];
        __nv_bfloat16 hi = __float2bfloat16(x);
        __nv_bfloat16 lo = __float2bfloat16(x - __bfloat162float(hi));
        g_hhi[0][i] = hi;
        g_hlo[0][i] = lo;
    }
}

// split fp32 -> bf16 hi/lo (vectorized, grid-stride)
__global__ void cvt_split(const float* __restrict__ src,
                          __nv_bfloat16* __restrict__ hi,
                          __nv_bfloat16* __restrict__ lo, int n4) {
    for (int i = blockIdx.x * blockDim.x + threadIdx.x; i < n4;
         i += gridDim.x * blockDim.x) {
        float4 v = *(const float4*)(src + (size_t)i * 4);
        __nv_bfloat16 h0 = __float2bfloat16(v.x);
        __nv_bfloat16 h1 = __float2bfloat16(v.y);
        __nv_bfloat16 h2 = __float2bfloat16(v.z);
        __nv_bfloat16 h3 = __float2bfloat16(v.w);
        __nv_bfloat162 hp0 = __halves2bfloat162(h0, h1);
        __nv_bfloat162 hp1 = __halves2bfloat162(h2, h3);
        __nv_bfloat162 lp0 = __halves2bfloat162(
            __float2bfloat16(v.x - __bfloat162float(h0)),
            __float2bfloat16(v.y - __bfloat162float(h1)));
        __nv_bfloat162 lp1 = __halves2bfloat162(
            __float2bfloat16(v.z - __bfloat162float(h2)),
            __float2bfloat16(v.w - __bfloat162float(h3)));
        *(uint2*)(hi + (size_t)i * 4) =
            make_uint2(*(unsigned*)&hp0, *(unsigned*)&hp1);
        *(uint2*)(lo + (size_t)i * 4) =
            make_uint2(*(unsigned*)&lp0, *(unsigned*)&lp1);
    }
}

// ---------------------------------------------------------------------------
// Phase 1: x_pre = input @ W_ih^T + (b_ih + b_hh)  via bf16-split HMMA.
// (byte-identical to the passing R8 kernel)
// ---------------------------------------------------------------------------
#define XPITCH 144
#define XT_SZ  (128 * XPITCH)
#define XSA_HI 0
#define XSA_LO (1 * XT_SZ)
#define XSW_HI (2 * XT_SZ)
#define XSW_LO (3 * XT_SZ)
#define XBUF   (4 * XT_SZ)
#define XS_BIAS (2 * XBUF)
#define XSMEM_REQ (XS_BIAS + 512 + 256)

__global__ __launch_bounds__(256, 1) void hmma_xpre(
    const float* __restrict__ bih, const float* __restrict__ bhh)
{
    extern __shared__ char xsm[];
    const uint32_t sb = smem_u32(xsm);

    const int tid  = threadIdx.x;
    const int wid  = tid >> 5;
    const int lane = tid & 31;
    const int m0 = blockIdx.y * 128;
    const int n0 = blockIdx.x * 128;

    if (tid < 128) {
        ((float*)(xsm + XS_BIAS))[tid] = bih[n0 + tid] + bhh[n0 + tid];
    }

    const int prow = tid >> 1;
    const int pseg0 = (tid & 1) * 4;
    auto load_chunk = [&](int kb, int buf) {
        uint32_t base = sb + (uint32_t)buf * XBUF;
        const __nv_bfloat16* ah = g_xhi + (size_t)(m0 + prow) * I_ + kb;
        const __nv_bfloat16* al = g_xlo + (size_t)(m0 + prow) * I_ + kb;
        const __nv_bfloat16* wh = g_whi + (size_t)(n0 + prow) * I_ + kb;
        const __nv_bfloat16* wl = g_wlo + (size_t)(n0 + prow) * I_ + kb;
        uint32_t ro = (uint32_t)prow * XPITCH;
#pragma unroll
        for (int s = 0; s < 4; s++) {
            int seg = pseg0 + s;
            uint32_t so = ro + (uint32_t)seg * 16;
            cp_async16(base + XSA_HI + so, ah + seg * 8);
            cp_async16(base + XSA_LO + so, al + seg * 8);
            cp_async16(base + XSW_HI + so, wh + seg * 8);
            cp_async16(base + XSW_LO + so, wl + seg * 8);
        }
    };

    const int wm = wid & 3;
    const int wn = wid >> 2;
    const uint32_t a_row  = (uint32_t)(wm * 32 + (lane & 15));
    const uint32_t a_kofs = (uint32_t)((lane >> 4) * 8);
    const uint32_t b_col  = (uint32_t)(wn * 64 + ((lane >> 4) << 3) + (lane & 7));
    const uint32_t b_kofs = (uint32_t)(((lane >> 3) & 1) * 8);

    float acc[2][8][4];
#pragma unroll
    for (int i = 0; i < 2; i++)
#pragma unroll
        for (int j = 0; j < 8; j++)
#pragma unroll
            for (int k = 0; k < 4; k++) acc[i][j][k] = 0.f;

    load_chunk(0, 0);
    cp_commit();

    for (int ch = 0; ch < 16; ch++) {
        if (ch < 15) {
            load_chunk((ch + 1) * 64, (ch + 1) & 1);
            cp_commit();
            cp_wait<1>();
        } else {
            cp_wait<0>();
        }
        __syncthreads();

        uint32_t bufb = sb + (uint32_t)(ch & 1) * XBUF;
#pragma unroll
        for (int ks = 0; ks < 4; ks++) {
            unsigned ahi0[4], ahi1[4], alo0[4], alo1[4];
            uint32_t ak = (uint32_t)(ks * 16) + a_kofs;
            uint32_t a0 = bufb + XSA_HI + a_row * XPITCH + ak * 2;
            uint32_t a1 = a0 + 16u * XPITCH;
            ldsm_x4(ahi0, a0);
            ldsm_x4(ahi1, a1);
            ldsm_x4(alo0, a0 + (XSA_LO - XSA_HI));
            ldsm_x4(alo1, a1 + (XSA_LO - XSA_HI));

#pragma unroll
            for (int ng = 0; ng < 4; ng++) {
                unsigned bh[4], bl[4];
                uint32_t bk = (uint32_t)(ks * 16) + b_kofs;
                uint32_t ba = bufb + XSW_HI + (b_col + ng * 16) * XPITCH + bk * 2;
                ldsm_x4(bh, ba);
                ldsm_x4(bl, ba + (XSW_LO - XSW_HI));

                mma16816(acc[0][ng * 2 + 0], ahi0, bh);
                mma16816(acc[0][ng * 2 + 1], ahi0, bh + 2);
                mma16816(acc[1][ng * 2 + 0], ahi1, bh);
                mma16816(acc[1][ng * 2 + 1], ahi1, bh + 2);
                mma16816(acc[0][ng * 2 + 0], alo0, bh);
                mma16816(acc[0][ng * 2 + 1], alo0, bh + 2);
                mma16816(acc[1][ng * 2 + 0], alo1, bh);
                mma16816(acc[1][ng * 2 + 1], alo1, bh + 2);
                mma16816(acc[0][ng * 2 + 0], ahi0, bl);
                mma16816(acc[0][ng * 2 + 1], ahi0, bl + 2);
                mma16816(acc[1][ng * 2 + 0], ahi1, bl);
                mma16816(acc[1][ng * 2 + 1], ahi1, bl + 2);
            }
        }
        __syncthreads();
    }

    const float* bias = (const float*)(xsm + XS_BIAS);
    const int gid = lane >> 2;
    const int tig = lane & 3;
#pragma unroll
    for (int mi = 0; mi < 2; mi++) {
        int r0 = m0 + wm * 32 + mi * 16 + gid;
#pragma unroll
        for (int f = 0; f < 8; f++) {
            int cl = wn * 64 + f * 8 + tig * 2;
            float b0 = bias[cl], b1 = bias[cl + 1];
            float* p0 = g_xpre + (size_t)r0 * G4 + n0 + cl;
            *(float2*)p0 = make_float2(acc[mi][f][0] + b0, acc[mi][f][1] + b1);
            float* p1 = p0 + (size_t)8 * G4;
            *(float2*)p1 = make_float2(acc[mi][f][2] + b0, acc[mi][f][3] + b1);
        }
    }
}

// ---------------------------------------------------------------------------
// Phase 2: persistent warp-MMA scan (R11: tree barrier + split accumulators).
// 128 CTAs x 256 thr (8 warps: 4 batch-groups x 2 col-groups).
// ---------------------------------------------------------------------------
#define W_PITCH_B 2064                 // 1032 bf16
#define A_PITCH_B 272                  // 136 bf16
#define SM_W_HI 0
#define SM_W_LO (SM_W_HI + 32 * W_PITCH_B)          // 66048
#define SM_A0   (SM_W_LO + 32 * W_PITCH_B)          // 132096
#define A_HALF  (64 * A_PITCH_B)                    // 17408
#define A_BUF   (2 * A_HALF)                        // 34816
#define SM_PS   (SM_A0 + 2 * A_BUF)                 // 201728
#define PS_PITCH 68
#define SMEM_NEED (SM_PS + 32 * PS_PITCH * 4)       // 210432
#define SMEM_REQ  (SMEM_NEED + 1024)

// Tree barrier: 8 groups of 16 CTAs -> root -> g_gen. Monotonic counters.
__device__ __forceinline__ void grid_barrier(unsigned target) {
    __syncthreads();
    if (threadIdx.x == 0) {
        unsigned g = (unsigned)blockIdx.x & 7u;
        unsigned p = atom_add_acqrel(&g_grp[g * 32]);
        if ((p & 15u) == 15u) {
            unsigned q = atom_add_acqrel(&g_root);
            if ((q & 7u) == 7u) {
                atom_add_release(&g_gen);
            }
        }
        while (ld_acq(&g_gen) < target) { __nanosleep(32); }
    }
    __syncthreads();
}

__global__ __launch_bounds__(NTHR, 1) void lstm_scan(
    const float* __restrict__ Whh,
    const float* __restrict__ c0,
    float* __restrict__ out)
{
    extern __shared__ char raw[];
    char* sm = (char*)(((uintptr_t)raw + 1023) & ~(uintptr_t)1023);
    const uint32_t sb = smem_u32(sm);

    const int tid  = threadIdx.x;
    const int wid  = tid >> 5;
    const int lane = tid & 31;
    const int j0   = blockIdx.x * 8;

    // --- preload W slice as bf16 hi/lo: row n (0..31) = gate col ---------
    for (int it = 0; it < 128; it++) {
        int e = it * 256 + tid;          // 32768 elements
        int n = e >> 10;
        int k = e & 1023;
        int wrow = (n >> 3) * H_ + j0 + (n & 7);
        float w = __ldg(Whh + (size_t)wrow * H_ + k);
        __nv_bfloat16 hi = __float2bfloat16(w);
        __nv_bfloat16 lo = __float2bfloat16(w - __bfloat162float(hi));
        *(__nv_bfloat16*)(sm + SM_W_HI + n * W_PITCH_B + k * 2) = hi;
        *(__nv_bfloat16*)(sm + SM_W_LO + n * W_PITCH_B + k * 2) = lo;
    }

    // --- c0 into registers: thread owns (b = tid>>2, j = (tid&3)*2 + q) --
    const int cb = tid >> 2;
    const int cj = (tid & 3) * 2;
    float creg[2];
    creg[0] = c0[cb * H_ + j0 + cj];
    creg[1] = c0[cb * H_ + j0 + cj + 1];
    __syncthreads();

    // --- MMA thread mapping ----------------------------------------------
    const int wb = wid & 3;              // batch group (16 rows)
    const int wc = wid >> 2;             // col group (16 cols)
    const int gid = lane >> 2;           // 0..7
    const int tig = lane & 3;            // 0..3

    const uint32_t a_row  = (uint32_t)(wb * 16 + (lane & 15));
    const uint32_t a_kofs = (uint32_t)((lane >> 4) * 8);
    const uint32_t b_row  = (uint32_t)(wc * 16 + ((lane >> 4) << 3) + (lane & 7));
    const uint32_t b_kofs = (uint32_t)(((lane >> 3) & 1) * 8);

    // cp.async A staging mapping
    const int prow = tid >> 4;           // 0..15 base row (i adds 16)
    const int pc16 = tid & 15;

    for (int t = 0; t < T_; t++) {
        // x_pre prefetch into registers (no h dependency -> before barrier)
        const float* xp = g_xpre + ((size_t)t * B_ + cb) * G4 + j0 + cj;
        float2 xr0 = __ldcs((const float2*)(xp));
        float2 xr1 = __ldcs((const float2*)(xp + H_));
        float2 xr2 = __ldcs((const float2*)(xp + 2 * H_));
        float2 xr3 = __ldcs((const float2*)(xp + 3 * H_));

        grid_barrier((unsigned)(t + 1));

        const __nv_bfloat16* hh = g_hhi[t & 1];
        const __nv_bfloat16* hl = g_hlo[t & 1];

        // split accumulators: 4 independent chains (h-term, correction-term)
        float acc0h[4] = {0.f, 0.f, 0.f, 0.f};
        float acc0c[4] = {0.f, 0.f, 0.f, 0.f};
        float acc1h[4] = {0.f, 0.f, 0.f, 0.f};
        float acc1c[4] = {0.f, 0.f, 0.f, 0.f};

        // issue chunk 0 -> buf 0
        {
            uint32_t base = sb + SM_A0;
#pragma unroll
            for (int i = 0; i < 4; i++) {
                int row = prow + i * 16;
                uint32_t doff = base + (uint32_t)(row * A_PITCH_B + pc16 * 16);
                size_t goff = (size_t)row * H_ + pc16 * 8;
                cp_async16(doff, hh + goff);
                cp_async16(doff + A_HALF, hl + goff);
            }
            cp_commit();
        }

        for (int ch = 0; ch < 8; ch++) {
            cp_wait<0>();
            __syncthreads();

            if (ch < 7) {
                uint32_t base = sb + SM_A0 + (uint32_t)((ch + 1) & 1) * A_BUF;
                int kbase = (ch + 1) * 128;
#pragma unroll
                for (int i = 0; i < 4; i++) {
                    int row = prow + i * 16;
                    uint32_t doff = base + (uint32_t)(row * A_PITCH_B + pc16 * 16);
                    size_t goff = (size_t)row * H_ + kbase + pc16 * 8;
                    cp_async16(doff, hh + goff);
                    cp_async16(doff + A_HALF, hl + goff);
                }
                cp_commit();
            }

            uint32_t abase = sb + SM_A0 + (uint32_t)(ch & 1) * A_BUF;
#pragma unroll
            for (int ks = 0; ks < 8; ks++) {
                unsigned ahi[4], alo[4], bh[4], bl[4];
                uint32_t ak = (uint32_t)(ks * 16) + a_kofs;
                uint32_t aaddr = abase + a_row * A_PITCH_B + ak * 2;
                ldsm_x4(ahi, aaddr);
                ldsm_x4(alo, aaddr + A_HALF);

                uint32_t bk = (uint32_t)(ch * 128 + ks * 16) + b_kofs;
                uint32_t baddr = sb + SM_W_HI + b_row * W_PITCH_B + bk * 2;
                ldsm_x4(bh, baddr);
                ldsm_x4(bl, baddr + (SM_W_LO - SM_W_HI));

                mma16816(acc0h, ahi, bh);
                mma16816(acc1h, ahi, bh + 2);
                mma16816(acc0c, alo, bh);
                mma16816(acc1c, alo, bh + 2);
                mma16816(acc0c, ahi, bl);
                mma16816(acc1c, ahi, bl + 2);
            }
        }
        __syncthreads();

        // --- exchange: ps[col][batch] (merge split accumulators) ---------
        float* ps = (float*)(sm + SM_PS);
        {
            int c0i = wc * 16 + tig * 2;
            int r0 = wb * 16 + gid;
            ps[(c0i + 0) * PS_PITCH + r0]     = acc0h[0] + acc0c[0];
            ps[(c0i + 1) * PS_PITCH + r0]     = acc0h[1] + acc0c[1];
            ps[(c0i + 0) * PS_PITCH + r0 + 8] = acc0h[2] + acc0c[2];
            ps[(c0i + 1) * PS_PITCH + r0 + 8] = acc0h[3] + acc0c[3];
            int c1i = c0i + 8;
            ps[(c1i + 0) * PS_PITCH + r0]     = acc1h[0] + acc1c[0];
            ps[(c1i + 1) * PS_PITCH + r0]     = acc1h[1] + acc1c[1];
            ps[(c1i + 0) * PS_PITCH + r0 + 8] = acc1h[2] + acc1c[2];
            ps[(c1i + 1) * PS_PITCH + r0 + 8] = acc1h[3] + acc1c[3];
        }
        __syncthreads();

        // --- gate combine: thread owns (cb, cj), (cb, cj+1) --------------
        float ht2[2];
#pragma unroll
        for (int q = 0; q < 2; q++) {
            int j = cj + q;
            float xi = q ? xr0.y : xr0.x;
            float xf = q ? xr1.y : xr1.x;
            float xo = q ? xr2.y : xr2.x;
            float xg = q ? xr3.y : xr3.x;
            float pi = ps[j * PS_PITCH + cb]        + xi;
            float pf = ps[(8 + j) * PS_PITCH + cb]  + xf;
            float po = ps[(16 + j) * PS_PITCH + cb] + xo;
            float pg = ps[(24 + j) * PS_PITCH + cb] + xg;

            float iv = 1.f / (1.f + expf(-pi));
            float fv = 1.f / (1.f + expf(-pf));
            float ov = 1.f / (1.f + expf(-po));
            float gv = tanhf(pg);

            float ct = fv * creg[q] + iv * gv;
            float hv = ov * tanhf(ct);
            creg[q] = ct;
            ht2[q] = hv;
        }

        // output (fp32, streaming) + next-h (bf16 hi/lo) stores
        __stcs((float2*)(out + ((size_t)t * B_ + cb) * H_ + j0 + cj),
               make_float2(ht2[0], ht2[1]));

        __nv_bfloat16 h0b = __float2bfloat16(ht2[0]);
        __nv_bfloat16 h1b = __float2bfloat16(ht2[1]);
        __nv_bfloat16 l0b = __float2bfloat16(ht2[0] - __bfloat162float(h0b));
        __nv_bfloat16 l1b = __float2bfloat16(ht2[1] - __bfloat162float(h1b));
        __nv_bfloat162 hp = __halves2bfloat162(h0b, h1b);
        __nv_bfloat162 lp = __halves2bfloat162(l0b, l1b);
        int hoff = cb * H_ + j0 + cj;
        __stcg((unsigned*)(g_hhi[(t + 1) & 1] + hoff), *(unsigned*)&hp);
        __stcg((unsigned*)(g_hlo[(t + 1) & 1] + hoff), *(unsigned*)&lp);

        if (t == T_ - 1) {
            *(float2*)(out + (size_t)T_ * B_ * H_ + hoff) =
                make_float2(ht2[0], ht2[1]);
            *(float2*)(out + (size_t)T_ * B_ * H_ + B_ * H_ + hoff) =
                make_float2(creg[0], creg[1]);
        }
        // release of h stores: next grid_barrier's acq_rel atomic chain
    }
}

// ---------------------------------------------------------------------------
extern "C" void kernel_launch(void* const* d_in, const int* in_sizes, int n_in,
                              void* d_out, int out_size) {
    const float* input = (const float*)d_in[0];   // [T,B,I]
    const float* h0    = (const float*)d_in[1];   // [1,B,H]
    const float* c0    = (const float*)d_in[2];   // [1,B,H]
    const float* W_ih  = (const float*)d_in[3];   // [4H,I]
    const float* b_ih  = (const float*)d_in[4];   // [4H]
    const float* W_hh  = (const float*)d_in[5];   // [4H,H]
    const float* b_hh  = (const float*)d_in[6];   // [4H]
    float* out = (float*)d_out;

    static int smem_set = 0;
    if (!smem_set) {
        cudaFuncSetAttribute(lstm_scan,
                             cudaFuncAttributeMaxDynamicSharedMemorySize,
                             SMEM_REQ);
        cudaFuncSetAttribute(hmma_xpre,
                             cudaFuncAttributeMaxDynamicSharedMemorySize,
                             XSMEM_REQ);
        smem_set = 1;
    }

    reset_barrier<<<1, 256>>>();
    init_state<<<(B_ * H_ + 255) / 256, 256>>>(h0);

    __nv_bfloat16 *xhi, *xlo, *whi, *wlo;
    cudaGetSymbolAddress((void**)&xhi, g_xhi);
    cudaGetSymbolAddress((void**)&xlo, g_xlo);
    cudaGetSymbolAddress((void**)&whi, g_whi);
    cudaGetSymbolAddress((void**)&wlo, g_wlo);

    cvt_split<<<2048, 256>>>(input, xhi, xlo, M_ * I_ / 4);
    cvt_split<<<1024, 256>>>(W_ih, whi, wlo, G4 * I_ / 4);

    hmma_xpre<<<dim3(G4 / 128, M_ / 128), 256, XSMEM_REQ>>>(b_ih, b_hh);
    lstm_scan<<<NBLK, NTHR, SMEM_REQ>>>(W_hh, c0, out);
}

// round 12
// speedup vs baseline: 1.2677x; 1.2677x over previous
#include <cuda_runtime.h>
#include <cuda_bf16.h>
#include <cuda_fp16.h>
#include <cstdint>
#include <cstddef>
#include <math.h>

#define T_  512
#define B_  64
#define I_  1024
#define H_  1024
#define G4  4096
#define M_  (T_ * B_)   // 32768
#define NBLK 128
#define NTHR 256

// ---------------------------------------------------------------------------
// Scratch (__device__ globals: allocation-free, harness-legal)
// ---------------------------------------------------------------------------
__device__ float g_xpre[(size_t)M_ * G4];            // [T*B, 4H] pre-activations
__device__ __half g_hf[2][B_ * H_];                  // h fp16 (ping-pong)
__device__ __nv_bfloat16 g_xhi[(size_t)M_ * I_];     // input hi bf16
__device__ __nv_bfloat16 g_xlo[(size_t)M_ * I_];     // input lo bf16
__device__ __nv_bfloat16 g_whi[(size_t)G4 * I_];     // W_ih hi bf16
__device__ __nv_bfloat16 g_wlo[(size_t)G4 * I_];     // W_ih lo bf16
__device__ unsigned g_gen;
__device__ unsigned g_arrive;

__device__ __forceinline__ unsigned ld_acq(unsigned* p) {
    unsigned v;
    asm volatile("ld.acquire.gpu.u32 %0, [%1];" : "=r"(v) : "l"(p) : "memory");
    return v;
}

// ---------------------------------------------------------------------------
// warp-MMA helpers (base-target PTX: sm_80+, compiles for sm_103)
// ---------------------------------------------------------------------------
__device__ __forceinline__ uint32_t smem_u32(const void* p) {
    uint32_t a;
    asm("{ .reg .u64 t; cvta.to.shared.u64 t, %1; cvt.u32.u64 %0, t; }"
        : "=r"(a) : "l"(p));
    return a;
}
__device__ __forceinline__ void ldsm_x4(unsigned* r, uint32_t addr) {
    asm volatile("ldmatrix.sync.aligned.m8n8.x4.shared.b16 {%0,%1,%2,%3}, [%4];"
                 : "=r"(r[0]), "=r"(r[1]), "=r"(r[2]), "=r"(r[3]) : "r"(addr));
}
__device__ __forceinline__ void mma16816(float* c, const unsigned* a,
                                         const unsigned* b) {
    asm volatile("mma.sync.aligned.m16n8k16.row.col.f32.bf16.bf16.f32 "
                 "{%0,%1,%2,%3}, {%4,%5,%6,%7}, {%8,%9}, {%0,%1,%2,%3};"
                 : "+f"(c[0]), "+f"(c[1]), "+f"(c[2]), "+f"(c[3])
                 : "r"(a[0]), "r"(a[1]), "r"(a[2]), "r"(a[3]),
                   "r"(b[0]), "r"(b[1]));
}
__device__ __forceinline__ void mma16816h(float* c, const unsigned* a,
                                          const unsigned* b) {
    asm volatile("mma.sync.aligned.m16n8k16.row.col.f32.f16.f16.f32 "
                 "{%0,%1,%2,%3}, {%4,%5,%6,%7}, {%8,%9}, {%0,%1,%2,%3};"
                 : "+f"(c[0]), "+f"(c[1]), "+f"(c[2]), "+f"(c[3])
                 : "r"(a[0]), "r"(a[1]), "r"(a[2]), "r"(a[3]),
                   "r"(b[0]), "r"(b[1]));
}
__device__ __forceinline__ void cp_async16(uint32_t daddr, const void* src) {
    asm volatile("cp.async.cg.shared.global [%0], [%1], 16;"
                 :: "r"(daddr), "l"(__cvta_generic_to_global(src)));
}
__device__ __forceinline__ void cp_commit() {
    asm volatile("cp.async.commit_group;");
}
template <int N>
__device__ __forceinline__ void cp_wait() {
    asm volatile("cp.async.wait_group %0;" :: "n"(N));
}

// ---------------------------------------------------------------------------
__global__ void reset_barrier() { g_gen = 0; g_arrive = 0; }

__global__ void init_state(const float* __restrict__ h0) {
    int i = blockIdx.x * blockDim.x + threadIdx.x;
    if (i < B_ * H_) {
        g_hf[0][i] = __float2half(h0[i]);
    }
}

// split fp32 -> bf16 hi/lo (vectorized, grid-stride)  [x_pre GEMM inputs]
__global__ void cvt_split(const float* __restrict__ src,
                          __nv_bfloat16* __restrict__ hi,
                          __nv_bfloat16* __restrict__ lo, int n4) {
    for (int i = blockIdx.x * blockDim.x + threadIdx.x; i < n4;
         i += gridDim.x * blockDim.x) {
        float4 v = *(const float4*)(src + (size_t)i * 4);
        __nv_bfloat16 h0 = __float2bfloat16(v.x);
        __nv_bfloat16 h1 = __float2bfloat16(v.y);
        __nv_bfloat16 h2 = __float2bfloat16(v.z);
        __nv_bfloat16 h3 = __float2bfloat16(v.w);
        __nv_bfloat162 hp0 = __halves2bfloat162(h0, h1);
        __nv_bfloat162 hp1 = __halves2bfloat162(h2, h3);
        __nv_bfloat162 lp0 = __halves2bfloat162(
            __float2bfloat16(v.x - __bfloat162float(h0)),
            __float2bfloat16(v.y - __bfloat162float(h1)));
        __nv_bfloat162 lp1 = __halves2bfloat162(
            __float2bfloat16(v.z - __bfloat162float(h2)),
            __float2bfloat16(v.w - __bfloat162float(h3)));
        *(uint2*)(hi + (size_t)i * 4) =
            make_uint2(*(unsigned*)&hp0, *(unsigned*)&hp1);
        *(uint2*)(lo + (size_t)i * 4) =
            make_uint2(*(unsigned*)&lp0, *(unsigned*)&lp1);
    }
}

// ---------------------------------------------------------------------------
// Phase 1: x_pre = input @ W_ih^T + (b_ih + b_hh)  via bf16-split HMMA.
// (byte-identical to the passing R8/R10 kernel)
// ---------------------------------------------------------------------------
#define XPITCH 144
#define XT_SZ  (128 * XPITCH)
#define XSA_HI 0
#define XSA_LO (1 * XT_SZ)
#define XSW_HI (2 * XT_SZ)
#define XSW_LO (3 * XT_SZ)
#define XBUF   (4 * XT_SZ)
#define XS_BIAS (2 * XBUF)
#define XSMEM_REQ (XS_BIAS + 512 + 256)

__global__ __launch_bounds__(256, 1) void hmma_xpre(
    const float* __restrict__ bih, const float* __restrict__ bhh)
{
    extern __shared__ char xsm[];
    const uint32_t sb = smem_u32(xsm);

    const int tid  = threadIdx.x;
    const int wid  = tid >> 5;
    const int lane = tid & 31;
    const int m0 = blockIdx.y * 128;
    const int n0 = blockIdx.x * 128;

    if (tid < 128) {
        ((float*)(xsm + XS_BIAS))[tid] = bih[n0 + tid] + bhh[n0 + tid];
    }

    const int prow = tid >> 1;
    const int pseg0 = (tid & 1) * 4;
    auto load_chunk = [&](int kb, int buf) {
        uint32_t base = sb + (uint32_t)buf * XBUF;
        const __nv_bfloat16* ah = g_xhi + (size_t)(m0 + prow) * I_ + kb;
        const __nv_bfloat16* al = g_xlo + (size_t)(m0 + prow) * I_ + kb;
        const __nv_bfloat16* wh = g_whi + (size_t)(n0 + prow) * I_ + kb;
        const __nv_bfloat16* wl = g_wlo + (size_t)(n0 + prow) * I_ + kb;
        uint32_t ro = (uint32_t)prow * XPITCH;
#pragma unroll
        for (int s = 0; s < 4; s++) {
            int seg = pseg0 + s;
            uint32_t so = ro + (uint32_t)seg * 16;
            cp_async16(base + XSA_HI + so, ah + seg * 8);
            cp_async16(base + XSA_LO + so, al + seg * 8);
            cp_async16(base + XSW_HI + so, wh + seg * 8);
            cp_async16(base + XSW_LO + so, wl + seg * 8);
        }
    };

    const int wm = wid & 3;
    const int wn = wid >> 2;
    const uint32_t a_row  = (uint32_t)(wm * 32 + (lane & 15));
    const uint32_t a_kofs = (uint32_t)((lane >> 4) * 8);
    const uint32_t b_col  = (uint32_t)(wn * 64 + ((lane >> 4) << 3) + (lane & 7));
    const uint32_t b_kofs = (uint32_t)(((lane >> 3) & 1) * 8);

    float acc[2][8][4];
#pragma unroll
    for (int i = 0; i < 2; i++)
#pragma unroll
        for (int j = 0; j < 8; j++)
#pragma unroll
            for (int k = 0; k < 4; k++) acc[i][j][k] = 0.f;

    load_chunk(0, 0);
    cp_commit();

    for (int ch = 0; ch < 16; ch++) {
        if (ch < 15) {
            load_chunk((ch + 1) * 64, (ch + 1) & 1);
            cp_commit();
            cp_wait<1>();
        } else {
            cp_wait<0>();
        }
        __syncthreads();

        uint32_t bufb = sb + (uint32_t)(ch & 1) * XBUF;
#pragma unroll
        for (int ks = 0; ks < 4; ks++) {
            unsigned ahi0[4], ahi1[4], alo0[4], alo1[4];
            uint32_t ak = (uint32_t)(ks * 16) + a_kofs;
            uint32_t a0 = bufb + XSA_HI + a_row * XPITCH + ak * 2;
            uint32_t a1 = a0 + 16u * XPITCH;
            ldsm_x4(ahi0, a0);
            ldsm_x4(ahi1, a1);
            ldsm_x4(alo0, a0 + (XSA_LO - XSA_HI));
            ldsm_x4(alo1, a1 + (XSA_LO - XSA_HI));

#pragma unroll
            for (int ng = 0; ng < 4; ng++) {
                unsigned bh[4], bl[4];
                uint32_t bk = (uint32_t)(ks * 16) + b_kofs;
                uint32_t ba = bufb + XSW_HI + (b_col + ng * 16) * XPITCH + bk * 2;
                ldsm_x4(bh, ba);
                ldsm_x4(bl, ba + (XSW_LO - XSW_HI));

                mma16816(acc[0][ng * 2 + 0], ahi0, bh);
                mma16816(acc[0][ng * 2 + 1], ahi0, bh + 2);
                mma16816(acc[1][ng * 2 + 0], ahi1, bh);
                mma16816(acc[1][ng * 2 + 1], ahi1, bh + 2);
                mma16816(acc[0][ng * 2 + 0], alo0, bh);
                mma16816(acc[0][ng * 2 + 1], alo0, bh + 2);
                mma16816(acc[1][ng * 2 + 0], alo1, bh);
                mma16816(acc[1][ng * 2 + 1], alo1, bh + 2);
                mma16816(acc[0][ng * 2 + 0], ahi0, bl);
                mma16816(acc[0][ng * 2 + 1], ahi0, bl + 2);
                mma16816(acc[1][ng * 2 + 0], ahi1, bl);
                mma16816(acc[1][ng * 2 + 1], ahi1, bl + 2);
            }
        }
        __syncthreads();
    }

    const float* bias = (const float*)(xsm + XS_BIAS);
    const int gid = lane >> 2;
    const int tig = lane & 3;
#pragma unroll
    for (int mi = 0; mi < 2; mi++) {
        int r0 = m0 + wm * 32 + mi * 16 + gid;
#pragma unroll
        for (int f = 0; f < 8; f++) {
            int cl = wn * 64 + f * 8 + tig * 2;
            float b0 = bias[cl], b1 = bias[cl + 1];
            float* p0 = g_xpre + (size_t)r0 * G4 + n0 + cl;
            *(float2*)p0 = make_float2(acc[mi][f][0] + b0, acc[mi][f][1] + b1);
            float* p1 = p0 + (size_t)8 * G4;
            *(float2*)p1 = make_float2(acc[mi][f][2] + b0, acc[mi][f][3] + b1);
        }
    }
}

// ---------------------------------------------------------------------------
// Phase 2: persistent warp-MMA scan — fp16 single-term (crossbar-bound fix).
// 128 CTAs x 256 thr (8 warps: 4 batch-groups x 2 col-groups).
// W slice fp16 resident in SMEM (64 KB); h ping-pongs as fp16 via L2.
// Per step: 8 k-chunks of 128 staged by cp.async (16 KB/chunk, 2 buffers);
// 2 MMAs per warp per k16. Crossbar bytes/step ~0.64 MB (was 1.5 MB).
// ---------------------------------------------------------------------------
#define W_PITCH_B 2064                 // 1024 fp16 = 2048 B + 16 pad
#define A_PITCH_B 272                  // 128 fp16 = 256 B + 16 pad
#define SM_W    0
#define SM_A0   (SM_W + 32 * W_PITCH_B)             // 66048
#define A_BUF   (64 * A_PITCH_B)                    // 17408
#define SM_PS   (SM_A0 + 2 * A_BUF)                 // 100864
#define PS_PITCH 68
#define SMEM_NEED (SM_PS + 32 * PS_PITCH * 4)       // 109568
#define SMEM_REQ  (SMEM_NEED + 1024)

__device__ __forceinline__ void grid_barrier(unsigned target) {
    __syncthreads();
    if (threadIdx.x == 0) {
        __threadfence();
        unsigned prev = atomicAdd(&g_arrive, 1u);
        if (prev == NBLK - 1) {
            atomicExch(&g_arrive, 0u);
            __threadfence();
            atomicAdd(&g_gen, 1u);
        } else {
            while (ld_acq(&g_gen) < target) { __nanosleep(32); }
        }
    }
    __syncthreads();
}

__global__ __launch_bounds__(NTHR, 1) void lstm_scan(
    const float* __restrict__ Whh,
    const float* __restrict__ c0,
    float* __restrict__ out)
{
    extern __shared__ char raw[];
    char* sm = (char*)(((uintptr_t)raw + 1023) & ~(uintptr_t)1023);
    const uint32_t sb = smem_u32(sm);

    const int tid  = threadIdx.x;
    const int wid  = tid >> 5;
    const int lane = tid & 31;
    const int j0   = blockIdx.x * 8;

    // --- preload W slice as fp16: row n (0..31) = gate col ---------------
    for (int it = 0; it < 128; it++) {
        int e = it * 256 + tid;          // 32768 elements
        int n = e >> 10;
        int k = e & 1023;
        int wrow = (n >> 3) * H_ + j0 + (n & 7);
        float w = __ldg(Whh + (size_t)wrow * H_ + k);
        *(__half*)(sm + SM_W + n * W_PITCH_B + k * 2) = __float2half(w);
    }

    // --- c0 into registers: thread owns (b = tid>>2, j = (tid&3)*2 + q) --
    const int cb = tid >> 2;
    const int cj = (tid & 3) * 2;
    float creg[2];
    creg[0] = c0[cb * H_ + j0 + cj];
    creg[1] = c0[cb * H_ + j0 + cj + 1];
    __syncthreads();

    // --- MMA thread mapping (verified lane maps from R7-R10) -------------
    const int wb = wid & 3;              // batch group (16 rows)
    const int wc = wid >> 2;             // col group (16 cols)
    const int gid = lane >> 2;           // 0..7
    const int tig = lane & 3;            // 0..3

    const uint32_t a_row  = (uint32_t)(wb * 16 + (lane & 15));
    const uint32_t a_kofs = (uint32_t)((lane >> 4) * 8);
    const uint32_t b_row  = (uint32_t)(wc * 16 + ((lane >> 4) << 3) + (lane & 7));
    const uint32_t b_kofs = (uint32_t)(((lane >> 3) & 1) * 8);

    // cp.async A staging: per chunk 64 rows x 256 B = 1024 x 16B pieces
    const int prow = tid >> 4;           // 0..15 base row (i adds 16)
    const int pseg = tid & 15;           // 16B piece within row

    for (int t = 0; t < T_; t++) {
        // x_pre prefetch into registers (no h dependency -> before barrier)
        const float* xp = g_xpre + ((size_t)t * B_ + cb) * G4 + j0 + cj;
        float2 xr0 = __ldcs((const float2*)(xp));
        float2 xr1 = __ldcs((const float2*)(xp + H_));
        float2 xr2 = __ldcs((const float2*)(xp + 2 * H_));
        float2 xr3 = __ldcs((const float2*)(xp + 3 * H_));

        grid_barrier((unsigned)(t + 1));

        const __half* hsrc = g_hf[t & 1];

        float acc0[4] = {0.f, 0.f, 0.f, 0.f};
        float acc1[4] = {0.f, 0.f, 0.f, 0.f};

        // issue chunk 0 -> buf 0
        {
            uint32_t base = sb + SM_A0;
#pragma unroll
            for (int i = 0; i < 4; i++) {
                int row = prow + i * 16;
                uint32_t doff = base + (uint32_t)(row * A_PITCH_B + pseg * 16);
                cp_async16(doff, hsrc + (size_t)row * H_ + pseg * 8);
            }
            cp_commit();
        }

        for (int ch = 0; ch < 8; ch++) {
            cp_wait<0>();
            __syncthreads();

            if (ch < 7) {
                uint32_t base = sb + SM_A0 + (uint32_t)((ch + 1) & 1) * A_BUF;
                int kbase = (ch + 1) * 128;
#pragma unroll
                for (int i = 0; i < 4; i++) {
                    int row = prow + i * 16;
                    uint32_t doff = base + (uint32_t)(row * A_PITCH_B + pseg * 16);
                    cp_async16(doff, hsrc + (size_t)row * H_ + kbase + pseg * 8);
                }
                cp_commit();
            }

            uint32_t abase = sb + SM_A0 + (uint32_t)(ch & 1) * A_BUF;
#pragma unroll
            for (int ks = 0; ks < 8; ks++) {
                unsigned ah[4], bh[4];
                uint32_t ak = (uint32_t)(ks * 16) + a_kofs;
                ldsm_x4(ah, abase + a_row * A_PITCH_B + ak * 2);

                uint32_t bk = (uint32_t)(ch * 128 + ks * 16) + b_kofs;
                ldsm_x4(bh, sb + SM_W + b_row * W_PITCH_B + bk * 2);

                mma16816h(acc0, ah, bh);
                mma16816h(acc1, ah, bh + 2);
            }
        }
        __syncthreads();

        // --- exchange: ps[col][batch] ------------------------------------
        float* ps = (float*)(sm + SM_PS);
        {
            int c0i = wc * 16 + tig * 2;
            int r0 = wb * 16 + gid;
            ps[(c0i + 0) * PS_PITCH + r0]     = acc0[0];
            ps[(c0i + 1) * PS_PITCH + r0]     = acc0[1];
            ps[(c0i + 0) * PS_PITCH + r0 + 8] = acc0[2];
            ps[(c0i + 1) * PS_PITCH + r0 + 8] = acc0[3];
            int c1i = c0i + 8;
            ps[(c1i + 0) * PS_PITCH + r0]     = acc1[0];
            ps[(c1i + 1) * PS_PITCH + r0]     = acc1[1];
            ps[(c1i + 0) * PS_PITCH + r0 + 8] = acc1[2];
            ps[(c1i + 1) * PS_PITCH + r0 + 8] = acc1[3];
        }
        __syncthreads();

        // --- gate combine: thread owns (cb, cj), (cb, cj+1) --------------
        float ht2[2];
#pragma unroll
        for (int q = 0; q < 2; q++) {
            int j = cj + q;
            float xi = q ? xr0.y : xr0.x;
            float xf = q ? xr1.y : xr1.x;
            float xo = q ? xr2.y : xr2.x;
            float xg = q ? xr3.y : xr3.x;
            float pi = ps[j * PS_PITCH + cb]        + xi;
            float pf = ps[(8 + j) * PS_PITCH + cb]  + xf;
            float po = ps[(16 + j) * PS_PITCH + cb] + xo;
            float pg = ps[(24 + j) * PS_PITCH + cb] + xg;

            float iv = 1.f / (1.f + expf(-pi));
            float fv = 1.f / (1.f + expf(-pf));
            float ov = 1.f / (1.f + expf(-po));
            float gv = tanhf(pg);

            float ct = fv * creg[q] + iv * gv;
            float hv = ov * tanhf(ct);
            creg[q] = ct;
            ht2[q] = hv;
        }

        // output (fp32, streaming) + next-h (fp16) stores
        __stcs((float2*)(out + ((size_t)t * B_ + cb) * H_ + j0 + cj),
               make_float2(ht2[0], ht2[1]));

        __half2 hp = __floats2half2_rn(ht2[0], ht2[1]);
        int hoff = cb * H_ + j0 + cj;
        __stcg((unsigned*)(g_hf[(t + 1) & 1] + hoff), *(unsigned*)&hp);

        if (t == T_ - 1) {
            *(float2*)(out + (size_t)T_ * B_ * H_ + hoff) =
                make_float2(ht2[0], ht2[1]);
            *(float2*)(out + (size_t)T_ * B_ * H_ + B_ * H_ + hoff) =
                make_float2(creg[0], creg[1]);
        }
        // release of h stores: next grid_barrier (sync + fence + atomic)
    }
}

// ---------------------------------------------------------------------------
extern "C" void kernel_launch(void* const* d_in, const int* in_sizes, int n_in,
                              void* d_out, int out_size) {
    const float* input = (const float*)d_in[0];   // [T,B,I]
    const float* h0    = (const float*)d_in[1];   // [1,B,H]
    const float* c0    = (const float*)d_in[2];   // [1,B,H]
    const float* W_ih  = (const float*)d_in[3];   // [4H,I]
    const float* b_ih  = (const float*)d_in[4];   // [4H]
    const float* W_hh  = (const float*)d_in[5];   // [4H,H]
    const float* b_hh  = (const float*)d_in[6];   // [4H]
    float* out = (float*)d_out;

    static int smem_set = 0;
    if (!smem_set) {
        cudaFuncSetAttribute(lstm_scan,
                             cudaFuncAttributeMaxDynamicSharedMemorySize,
                             SMEM_REQ);
        cudaFuncSetAttribute(hmma_xpre,
                             cudaFuncAttributeMaxDynamicSharedMemorySize,
                             XSMEM_REQ);
        smem_set = 1;
    }

    reset_barrier<<<1, 1>>>();
    init_state<<<(B_ * H_ + 255) / 256, 256>>>(h0);

    __nv_bfloat16 *xhi, *xlo, *whi, *wlo;
    cudaGetSymbolAddress((void**)&xhi, g_xhi);
    cudaGetSymbolAddress((void**)&xlo, g_xlo);
    cudaGetSymbolAddress((void**)&whi, g_whi);
    cudaGetSymbolAddress((void**)&wlo, g_wlo);

    cvt_split<<<2048, 256>>>(input, xhi, xlo, M_ * I_ / 4);
    cvt_split<<<1024, 256>>>(W_ih, whi, wlo, G4 * I_ / 4);

    hmma_xpre<<<dim3(G4 / 128, M_ / 128), 256, XSMEM_REQ>>>(b_ih, b_hh);
    lstm_scan<<<NBLK, NTHR, SMEM_REQ>>>(W_hh, c0, out);
}

// round 15
// speedup vs baseline: 1.3783x; 1.0872x over previous
#include <cuda_runtime.h>
#include <cuda_bf16.h>
#include <cuda_fp16.h>
#include <cstdint>
#include <cstddef>
#include <math.h>

#define T_  512
#define B_  64
#define I_  1024
#define H_  1024
#define G4  4096
#define M_  (T_ * B_)   // 32768
#define NBLK 128
#define NTHR 256

// ---------------------------------------------------------------------------
// Scratch (__device__ globals: allocation-free, harness-legal)
// ---------------------------------------------------------------------------
__device__ float g_xpre[(size_t)M_ * G4];            // [T*B, 4H] pre-activations
__device__ __half g_hf[2][B_ * H_];                  // h fp16 (ping-pong)
__device__ __nv_bfloat16 g_xhi[(size_t)M_ * I_];     // input hi bf16
__device__ __nv_bfloat16 g_xlo[(size_t)M_ * I_];     // input lo bf16
__device__ __nv_bfloat16 g_whi[(size_t)G4 * I_];     // W_ih hi bf16
__device__ __nv_bfloat16 g_wlo[(size_t)G4 * I_];     // W_ih lo bf16
__device__ unsigned g_gen;
__device__ unsigned g_arrive;

__device__ __forceinline__ unsigned ld_acq(unsigned* p) {
    unsigned v;
    asm volatile("ld.acquire.gpu.u32 %0, [%1];" : "=r"(v) : "l"(p) : "memory");
    return v;
}

// ---------------------------------------------------------------------------
// warp-MMA helpers (base-target PTX: sm_80+, compiles for sm_103)
// ---------------------------------------------------------------------------
__device__ __forceinline__ uint32_t smem_u32(const void* p) {
    uint32_t a;
    asm("{ .reg .u64 t; cvta.to.shared.u64 t, %1; cvt.u32.u64 %0, t; }"
        : "=r"(a) : "l"(p));
    return a;
}
__device__ __forceinline__ void ldsm_x4(unsigned* r, uint32_t addr) {
    asm volatile("ldmatrix.sync.aligned.m8n8.x4.shared.b16 {%0,%1,%2,%3}, [%4];"
                 : "=r"(r[0]), "=r"(r[1]), "=r"(r[2]), "=r"(r[3]) : "r"(addr));
}
__device__ __forceinline__ void mma16816(float* c, const unsigned* a,
                                         const unsigned* b) {
    asm volatile("mma.sync.aligned.m16n8k16.row.col.f32.bf16.bf16.f32 "
                 "{%0,%1,%2,%3}, {%4,%5,%6,%7}, {%8,%9}, {%0,%1,%2,%3};"
                 : "+f"(c[0]), "+f"(c[1]), "+f"(c[2]), "+f"(c[3])
                 : "r"(a[0]), "r"(a[1]), "r"(a[2]), "r"(a[3]),
                   "r"(b[0]), "r"(b[1]));
}
__device__ __forceinline__ void mma16816h(float* c, const unsigned* a,
                                          const unsigned* b) {
    asm volatile("mma.sync.aligned.m16n8k16.row.col.f32.f16.f16.f32 "
                 "{%0,%1,%2,%3}, {%4,%5,%6,%7}, {%8,%9}, {%0,%1,%2,%3};"
                 : "+f"(c[0]), "+f"(c[1]), "+f"(c[2]), "+f"(c[3])
                 : "r"(a[0]), "r"(a[1]), "r"(a[2]), "r"(a[3]),
                   "r"(b[0]), "r"(b[1]));
}
__device__ __forceinline__ void cp_async16(uint32_t daddr, const void* src) {
    asm volatile("cp.async.cg.shared.global [%0], [%1], 16;"
                 :: "r"(daddr), "l"(__cvta_generic_to_global(src)));
}
__device__ __forceinline__ void cp_commit() {
    asm volatile("cp.async.commit_group;");
}
template <int N>
__device__ __forceinline__ void cp_wait() {
    asm volatile("cp.async.wait_group %0;" :: "n"(N));
}

// ---------------------------------------------------------------------------
__global__ void reset_barrier() { g_gen = 0; g_arrive = 0; }

__global__ void init_state(const float* __restrict__ h0) {
    int i = blockIdx.x * blockDim.x + threadIdx.x;
    if (i < B_ * H_) {
        g_hf[0][i] = __float2half(h0[i]);
    }
}

// split fp32 -> bf16 hi/lo (vectorized, grid-stride)  [x_pre GEMM inputs]
__global__ void cvt_split(const float* __restrict__ src,
                          __nv_bfloat16* __restrict__ hi,
                          __nv_bfloat16* __restrict__ lo, int n4) {
    for (int i = blockIdx.x * blockDim.x + threadIdx.x; i < n4;
         i += gridDim.x * blockDim.x) {
        float4 v = *(const float4*)(src + (size_t)i * 4);
        __nv_bfloat16 h0 = __float2bfloat16(v.x);
        __nv_bfloat16 h1 = __float2bfloat16(v.y);
        __nv_bfloat16 h2 = __float2bfloat16(v.z);
        __nv_bfloat16 h3 = __float2bfloat16(v.w);
        __nv_bfloat162 hp0 = __halves2bfloat162(h0, h1);
        __nv_bfloat162 hp1 = __halves2bfloat162(h2, h3);
        __nv_bfloat162 lp0 = __halves2bfloat162(
            __float2bfloat16(v.x - __bfloat162float(h0)),
            __float2bfloat16(v.y - __bfloat162float(h1)));
        __nv_bfloat162 lp1 = __halves2bfloat162(
            __float2bfloat16(v.z - __bfloat162float(h2)),
            __float2bfloat16(v.w - __bfloat162float(h3)));
        *(uint2*)(hi + (size_t)i * 4) =
            make_uint2(*(unsigned*)&hp0, *(unsigned*)&hp1);
        *(uint2*)(lo + (size_t)i * 4) =
            make_uint2(*(unsigned*)&lp0, *(unsigned*)&lp1);
    }
}

// ---------------------------------------------------------------------------
// Phase 1: x_pre = input @ W_ih^T + (b_ih + b_hh)  via bf16-split HMMA.
// (byte-identical to the passing R8/R10/R12 kernel)
// ---------------------------------------------------------------------------
#define XPITCH 144
#define XT_SZ  (128 * XPITCH)
#define XSA_HI 0
#define XSA_LO (1 * XT_SZ)
#define XSW_HI (2 * XT_SZ)
#define XSW_LO (3 * XT_SZ)
#define XBUF   (4 * XT_SZ)
#define XS_BIAS (2 * XBUF)
#define XSMEM_REQ (XS_BIAS + 512 + 256)

__global__ __launch_bounds__(256, 1) void hmma_xpre(
    const float* __restrict__ bih, const float* __restrict__ bhh)
{
    extern __shared__ char xsm[];
    const uint32_t sb = smem_u32(xsm);

    const int tid  = threadIdx.x;
    const int wid  = tid >> 5;
    const int lane = tid & 31;
    const int m0 = blockIdx.y * 128;
    const int n0 = blockIdx.x * 128;

    if (tid < 128) {
        ((float*)(xsm + XS_BIAS))[tid] = bih[n0 + tid] + bhh[n0 + tid];
    }

    const int prow = tid >> 1;
    const int pseg0 = (tid & 1) * 4;
    auto load_chunk = [&](int kb, int buf) {
        uint32_t base = sb + (uint32_t)buf * XBUF;
        const __nv_bfloat16* ah = g_xhi + (size_t)(m0 + prow) * I_ + kb;
        const __nv_bfloat16* al = g_xlo + (size_t)(m0 + prow) * I_ + kb;
        const __nv_bfloat16* wh = g_whi + (size_t)(n0 + prow) * I_ + kb;
        const __nv_bfloat16* wl = g_wlo + (size_t)(n0 + prow) * I_ + kb;
        uint32_t ro = (uint32_t)prow * XPITCH;
#pragma unroll
        for (int s = 0; s < 4; s++) {
            int seg = pseg0 + s;
            uint32_t so = ro + (uint32_t)seg * 16;
            cp_async16(base + XSA_HI + so, ah + seg * 8);
            cp_async16(base + XSA_LO + so, al + seg * 8);
            cp_async16(base + XSW_HI + so, wh + seg * 8);
            cp_async16(base + XSW_LO + so, wl + seg * 8);
        }
    };

    const int wm = wid & 3;
    const int wn = wid >> 2;
    const uint32_t a_row  = (uint32_t)(wm * 32 + (lane & 15));
    const uint32_t a_kofs = (uint32_t)((lane >> 4) * 8);
    const uint32_t b_col  = (uint32_t)(wn * 64 + ((lane >> 4) << 3) + (lane & 7));
    const uint32_t b_kofs = (uint32_t)(((lane >> 3) & 1) * 8);

    float acc[2][8][4];
#pragma unroll
    for (int i = 0; i < 2; i++)
#pragma unroll
        for (int j = 0; j < 8; j++)
#pragma unroll
            for (int k = 0; k < 4; k++) acc[i][j][k] = 0.f;

    load_chunk(0, 0);
    cp_commit();

    for (int ch = 0; ch < 16; ch++) {
        if (ch < 15) {
            load_chunk((ch + 1) * 64, (ch + 1) & 1);
            cp_commit();
            cp_wait<1>();
        } else {
            cp_wait<0>();
        }
        __syncthreads();

        uint32_t bufb = sb + (uint32_t)(ch & 1) * XBUF;
#pragma unroll
        for (int ks = 0; ks < 4; ks++) {
            unsigned ahi0[4], ahi1[4], alo0[4], alo1[4];
            uint32_t ak = (uint32_t)(ks * 16) + a_kofs;
            uint32_t a0 = bufb + XSA_HI + a_row * XPITCH + ak * 2;
            uint32_t a1 = a0 + 16u * XPITCH;
            ldsm_x4(ahi0, a0);
            ldsm_x4(ahi1, a1);
            ldsm_x4(alo0, a0 + (XSA_LO - XSA_HI));
            ldsm_x4(alo1, a1 + (XSA_LO - XSA_HI));

#pragma unroll
            for (int ng = 0; ng < 4; ng++) {
                unsigned bh[4], bl[4];
                uint32_t bk = (uint32_t)(ks * 16) + b_kofs;
                uint32_t ba = bufb + XSW_HI + (b_col + ng * 16) * XPITCH + bk * 2;
                ldsm_x4(bh, ba);
                ldsm_x4(bl, ba + (XSW_LO - XSW_HI));

                mma16816(acc[0][ng * 2 + 0], ahi0, bh);
                mma16816(acc[0][ng * 2 + 1], ahi0, bh + 2);
                mma16816(acc[1][ng * 2 + 0], ahi1, bh);
                mma16816(acc[1][ng * 2 + 1], ahi1, bh + 2);
                mma16816(acc[0][ng * 2 + 0], alo0, bh);
                mma16816(acc[0][ng * 2 + 1], alo0, bh + 2);
                mma16816(acc[1][ng * 2 + 0], alo1, bh);
                mma16816(acc[1][ng * 2 + 1], alo1, bh + 2);
                mma16816(acc[0][ng * 2 + 0], ahi0, bl);
                mma16816(acc[0][ng * 2 + 1], ahi0, bl + 2);
                mma16816(acc[1][ng * 2 + 0], ahi1, bl);
                mma16816(acc[1][ng * 2 + 1], ahi1, bl + 2);
            }
        }
        __syncthreads();
    }

    const float* bias = (const float*)(xsm + XS_BIAS);
    const int gid = lane >> 2;
    const int tig = lane & 3;
#pragma unroll
    for (int mi = 0; mi < 2; mi++) {
        int r0 = m0 + wm * 32 + mi * 16 + gid;
#pragma unroll
        for (int f = 0; f < 8; f++) {
            int cl = wn * 64 + f * 8 + tig * 2;
            float b0 = bias[cl], b1 = bias[cl + 1];
            float* p0 = g_xpre + (size_t)r0 * G4 + n0 + cl;
            *(float2*)p0 = make_float2(acc[mi][f][0] + b0, acc[mi][f][1] + b1);
            float* p1 = p0 + (size_t)8 * G4;
            *(float2*)p1 = make_float2(acc[mi][f][2] + b0, acc[mi][f][3] + b1);
        }
    }
}

// ---------------------------------------------------------------------------
// Phase 2: persistent warp-MMA scan — fp16, half-K double buffer.
// 128 CTAs x 256 thr (8 warps: 4 batch-groups x 2 col-groups).
// W slice fp16 resident in SMEM; h staged in 2 half-K buffers (64 x 512 fp16,
// pitch 1040 = 16 mod 128 -> conflict-free LDSM). Both halves issued up
// front; compute half0 overlaps half1 transfer. 2 syncthreads/step.
// ---------------------------------------------------------------------------
#define W_PITCH_B 2064                 // 1024 fp16 + 16 pad
#define A_PITCH_B 1040                 // 512 fp16 + 16 pad (=16 mod 128)
#define SM_W    0
#define SM_A0   (SM_W + 32 * W_PITCH_B)             // 66048
#define A_BUF   (64 * A_PITCH_B)                    // 66560
#define SM_PS   (SM_A0 + 2 * A_BUF)                 // 199168
#define PS_PITCH 68
#define SMEM_NEED (SM_PS + 32 * PS_PITCH * 4)       // 207872
#define SMEM_REQ  (SMEM_NEED + 1024)

__device__ __forceinline__ void grid_barrier(unsigned target) {
    __syncthreads();
    if (threadIdx.x == 0) {
        __threadfence();
        unsigned prev = atomicAdd(&g_arrive, 1u);
        if (prev == NBLK - 1) {
            atomicExch(&g_arrive, 0u);
            __threadfence();
            atomicAdd(&g_gen, 1u);
        } else {
            while (ld_acq(&g_gen) < target) { __nanosleep(32); }
        }
    }
    __syncthreads();
}

__global__ __launch_bounds__(NTHR, 1) void lstm_scan(
    const float* __restrict__ Whh,
    const float* __restrict__ c0,
    float* __restrict__ out)
{
    extern __shared__ char raw[];
    char* sm = (char*)(((uintptr_t)raw + 1023) & ~(uintptr_t)1023);
    const uint32_t sb = smem_u32(sm);

    const int tid  = threadIdx.x;
    const int wid  = tid >> 5;
    const int lane = tid & 31;
    const int j0   = blockIdx.x * 8;

    // --- preload W slice as fp16: row n (0..31) = gate col ---------------
    for (int it = 0; it < 128; it++) {
        int e = it * 256 + tid;          // 32768 elements
        int n = e >> 10;
        int k = e & 1023;
        int wrow = (n >> 3) * H_ + j0 + (n & 7);
        float w = __ldg(Whh + (size_t)wrow * H_ + k);
        *(__half*)(sm + SM_W + n * W_PITCH_B + k * 2) = __float2half(w);
    }

    // --- c0 into registers: thread owns (b = tid>>2, j = (tid&3)*2 + q) --
    const int cb = tid >> 2;
    const int cj = (tid & 3) * 2;
    float creg[2];
    creg[0] = c0[cb * H_ + j0 + cj];
    creg[1] = c0[cb * H_ + j0 + cj + 1];
    __syncthreads();

    // --- MMA thread mapping (verified lane maps) --------------------------
    const int wb = wid & 3;              // batch group (16 rows)
    const int wc = wid >> 2;             // col group (16 cols)
    const int gid = lane >> 2;           // 0..7
    const int tig = lane & 3;            // 0..3

    const uint32_t a_row  = (uint32_t)(wb * 16 + (lane & 15));
    const uint32_t a_kofs = (uint32_t)((lane >> 4) * 8);
    const uint32_t b_row  = (uint32_t)(wc * 16 + ((lane >> 4) << 3) + (lane & 7));
    const uint32_t b_kofs = (uint32_t)(((lane >> 3) & 1) * 8);

    for (int t = 0; t < T_; t++) {
        // x_pre prefetch into registers (no h dependency -> before barrier)
        const float* xp = g_xpre + ((size_t)t * B_ + cb) * G4 + j0 + cj;
        float2 xr0 = __ldcs((const float2*)(xp));
        float2 xr1 = __ldcs((const float2*)(xp + H_));
        float2 xr2 = __ldcs((const float2*)(xp + 2 * H_));
        float2 xr3 = __ldcs((const float2*)(xp + 3 * H_));

        grid_barrier((unsigned)(t + 1));

        const __half* hsrc = g_hf[t & 1];

        float acc0[4] = {0.f, 0.f, 0.f, 0.f};
        float acc1[4] = {0.f, 0.f, 0.f, 0.f};

        // issue BOTH half-K buffers up front (one commit group per half)
#pragma unroll
        for (int half = 0; half < 2; half++) {
            uint32_t base = sb + SM_A0 + (uint32_t)half * A_BUF;
            const __half* src = hsrc + half * 512;
#pragma unroll
            for (int i = 0; i < 16; i++) {
                int piece = i * 256 + tid;       // 0..4095
                int row = piece >> 6;            // 0..63
                int seg = piece & 63;            // 16B piece within 1024B row
                cp_async16(base + (uint32_t)(row * A_PITCH_B + seg * 16),
                           src + (size_t)row * H_ + seg * 8);
            }
            cp_commit();
        }

#pragma unroll
        for (int half = 0; half < 2; half++) {
            if (half == 0) cp_wait<1>(); else cp_wait<0>();
            __syncthreads();

            uint32_t abase = sb + SM_A0 + (uint32_t)half * A_BUF;
            uint32_t wbase = sb + SM_W + (uint32_t)half * 1024u;  // 512 fp16
#pragma unroll 8
            for (int ks = 0; ks < 32; ks++) {
                unsigned ah[4], bh[4];
                ldsm_x4(ah, abase + a_row * A_PITCH_B
                            + (uint32_t)ks * 32 + a_kofs * 2);
                ldsm_x4(bh, wbase + b_row * W_PITCH_B
                            + (uint32_t)ks * 32 + b_kofs * 2);
                mma16816h(acc0, ah, bh);
                mma16816h(acc1, ah, bh + 2);
            }
        }
        __syncthreads();

        // --- exchange: ps[col][batch] ------------------------------------
        float* ps = (float*)(sm + SM_PS);
        {
            int c0i = wc * 16 + tig * 2;
            int r0 = wb * 16 + gid;
            ps[(c0i + 0) * PS_PITCH + r0]     = acc0[0];
            ps[(c0i + 1) * PS_PITCH + r0]     = acc0[1];
            ps[(c0i + 0) * PS_PITCH + r0 + 8] = acc0[2];
            ps[(c0i + 1) * PS_PITCH + r0 + 8] = acc0[3];
            int c1i = c0i + 8;
            ps[(c1i + 0) * PS_PITCH + r0]     = acc1[0];
            ps[(c1i + 1) * PS_PITCH + r0]     = acc1[1];
            ps[(c1i + 0) * PS_PITCH + r0 + 8] = acc1[2];
            ps[(c1i + 1) * PS_PITCH + r0 + 8] = acc1[3];
        }
        __syncthreads();

        // --- gate combine: thread owns (cb, cj), (cb, cj+1) --------------
        float ht2[2];
#pragma unroll
        for (int q = 0; q < 2; q++) {
            int j = cj + q;
            float xi = q ? xr0.y : xr0.x;
            float xf = q ? xr1.y : xr1.x;
            float xo = q ? xr2.y : xr2.x;
            float xg = q ? xr3.y : xr3.x;
            float pi = ps[j * PS_PITCH + cb]        + xi;
            float pf = ps[(8 + j) * PS_PITCH + cb]  + xf;
            float po = ps[(16 + j) * PS_PITCH + cb] + xo;
            float pg = ps[(24 + j) * PS_PITCH + cb] + xg;

            float iv = 1.f / (1.f + expf(-pi));
            float fv = 1.f / (1.f + expf(-pf));
            float ov = 1.f / (1.f + expf(-po));
            float gv = tanhf(pg);

            float ct = fv * creg[q] + iv * gv;
            float hv = ov * tanhf(ct);
            creg[q] = ct;
            ht2[q] = hv;
        }

        // output (fp32, streaming) + next-h (fp16) stores
        __stcs((float2*)(out + ((size_t)t * B_ + cb) * H_ + j0 + cj),
               make_float2(ht2[0], ht2[1]));

        __half2 hp = __floats2half2_rn(ht2[0], ht2[1]);
        int hoff = cb * H_ + j0 + cj;
        __stcg((unsigned*)(g_hf[(t + 1) & 1] + hoff), *(unsigned*)&hp);

        if (t == T_ - 1) {
            *(float2*)(out + (size_t)T_ * B_ * H_ + hoff) =
                make_float2(ht2[0], ht2[1]);
            *(float2*)(out + (size_t)T_ * B_ * H_ + B_ * H_ + hoff) =
                make_float2(creg[0], creg[1]);
        }
        // release of h stores: next grid_barrier (sync + fence + atomic)
    }
}

// ---------------------------------------------------------------------------
extern "C" void kernel_launch(void* const* d_in, const int* in_sizes, int n_in,
                              void* d_out, int out_size) {
    const float* input = (const float*)d_in[0];   // [T,B,I]
    const float* h0    = (const float*)d_in[1];   // [1,B,H]
    const float* c0    = (const float*)d_in[2];   // [1,B,H]
    const float* W_ih  = (const float*)d_in[3];   // [4H,I]
    const float* b_ih  = (const float*)d_in[4];   // [4H]
    const float* W_hh  = (const float*)d_in[5];   // [4H,H]
    const float* b_hh  = (const float*)d_in[6];   // [4H]
    float* out = (float*)d_out;

    static int smem_set = 0;
    if (!smem_set) {
        cudaFuncSetAttribute(lstm_scan,
                             cudaFuncAttributeMaxDynamicSharedMemorySize,
                             SMEM_REQ);
        cudaFuncSetAttribute(hmma_xpre,
                             cudaFuncAttributeMaxDynamicSharedMemorySize,
                             XSMEM_REQ);
        smem_set = 1;
    }

    reset_barrier<<<1, 1>>>();
    init_state<<<(B_ * H_ + 255) / 256, 256>>>(h0);

    __nv_bfloat16 *xhi, *xlo, *whi, *wlo;
    cudaGetSymbolAddress((void**)&xhi, g_xhi);
    cudaGetSymbolAddress((void**)&xlo, g_xlo);
    cudaGetSymbolAddress((void**)&whi, g_whi);
    cudaGetSymbolAddress((void**)&wlo, g_wlo);

    cvt_split<<<2048, 256>>>(input, xhi, xlo, M_ * I_ / 4);
    cvt_split<<<1024, 256>>>(W_ih, whi, wlo, G4 * I_ / 4);

    hmma_xpre<<<dim3(G4 / 128, M_ / 128), 256, XSMEM_REQ>>>(b_ih, b_hh);
    lstm_scan<<<NBLK, NTHR, SMEM_REQ>>>(W_hh, c0, out);
}

// round 16
// speedup vs baseline: 1.7862x; 1.2960x over previous
#include <cuda_runtime.h>
#include <cuda_bf16.h>
#include <cuda_fp16.h>
#include <cstdint>
#include <cstddef>
#include <math.h>

#define T_  512
#define B_  64
#define I_  1024
#define H_  1024
#define G4  4096
#define M_  (T_ * B_)   // 32768
#define NBLK 128
#define NTHR 256

// ---------------------------------------------------------------------------
// Scratch (__device__ globals: allocation-free, harness-legal)
// ---------------------------------------------------------------------------
__device__ float g_xpre[(size_t)M_ * G4];            // [T*B, 4H] pre-activations
__device__ __half g_hf[2][B_ * H_];                  // h fp16 (ping-pong)
__device__ __half g_xf[(size_t)M_ * I_];             // input fp16
__device__ __half g_wf[(size_t)G4 * I_];             // W_ih fp16
__device__ unsigned g_gen;
__device__ unsigned g_arrive;

__device__ __forceinline__ unsigned ld_acq(unsigned* p) {
    unsigned v;
    asm volatile("ld.acquire.gpu.u32 %0, [%1];" : "=r"(v) : "l"(p) : "memory");
    return v;
}

// ---------------------------------------------------------------------------
// warp-MMA helpers (base-target PTX: sm_80+, compiles for sm_103)
// ---------------------------------------------------------------------------
__device__ __forceinline__ uint32_t smem_u32(const void* p) {
    uint32_t a;
    asm("{ .reg .u64 t; cvta.to.shared.u64 t, %1; cvt.u32.u64 %0, t; }"
        : "=r"(a) : "l"(p));
    return a;
}
__device__ __forceinline__ void ldsm_x4(unsigned* r, uint32_t addr) {
    asm volatile("ldmatrix.sync.aligned.m8n8.x4.shared.b16 {%0,%1,%2,%3}, [%4];"
                 : "=r"(r[0]), "=r"(r[1]), "=r"(r[2]), "=r"(r[3]) : "r"(addr));
}
__device__ __forceinline__ void mma16816h(float* c, const unsigned* a,
                                          const unsigned* b) {
    asm volatile("mma.sync.aligned.m16n8k16.row.col.f32.f16.f16.f32 "
                 "{%0,%1,%2,%3}, {%4,%5,%6,%7}, {%8,%9}, {%0,%1,%2,%3};"
                 : "+f"(c[0]), "+f"(c[1]), "+f"(c[2]), "+f"(c[3])
                 : "r"(a[0]), "r"(a[1]), "r"(a[2]), "r"(a[3]),
                   "r"(b[0]), "r"(b[1]));
}
__device__ __forceinline__ void cp_async16(uint32_t daddr, const void* src) {
    asm volatile("cp.async.cg.shared.global [%0], [%1], 16;"
                 :: "r"(daddr), "l"(__cvta_generic_to_global(src)));
}
__device__ __forceinline__ void cp_commit() {
    asm volatile("cp.async.commit_group;");
}
template <int N>
__device__ __forceinline__ void cp_wait() {
    asm volatile("cp.async.wait_group %0;" :: "n"(N));
}

// ---------------------------------------------------------------------------
__global__ void reset_barrier() { g_gen = 0; g_arrive = 0; }

__global__ void init_state(const float* __restrict__ h0) {
    int i = blockIdx.x * blockDim.x + threadIdx.x;
    if (i < B_ * H_) {
        g_hf[0][i] = __float2half(h0[i]);
    }
}

// fp32 -> fp16 convert (vectorized, grid-stride)
__global__ void cvt_half(const float* __restrict__ src,
                         __half* __restrict__ dst, int n4) {
    for (int i = blockIdx.x * blockDim.x + threadIdx.x; i < n4;
         i += gridDim.x * blockDim.x) {
        float4 v = *(const float4*)(src + (size_t)i * 4);
        __half2 h01 = __floats2half2_rn(v.x, v.y);
        __half2 h23 = __floats2half2_rn(v.z, v.w);
        *(uint2*)(dst + (size_t)i * 4) =
            make_uint2(*(unsigned*)&h01, *(unsigned*)&h23);
    }
}

// ---------------------------------------------------------------------------
// Phase 1: x_pre = input @ W_ih^T + (b_ih + b_hh)  via fp16 HMMA (R16).
// 128x128 tiles, kc=64, 8 warps (4m x 2n), warp tile 32x64.
// cp.async double-buffered; single-term fp16 (4 MMAs per ng-iter).
// ---------------------------------------------------------------------------
#define XPITCH 144
#define XT_SZ  (128 * XPITCH)          // 18432
#define XSA    0
#define XSW    XT_SZ
#define XBUF   (2 * XT_SZ)             // 36864 per stage
#define XS_BIAS (2 * XBUF)             // 73728
#define XSMEM_REQ (XS_BIAS + 512 + 256)

__global__ __launch_bounds__(256, 1) void hmma_xpre(
    const float* __restrict__ bih, const float* __restrict__ bhh)
{
    extern __shared__ char xsm[];
    const uint32_t sb = smem_u32(xsm);

    const int tid  = threadIdx.x;
    const int wid  = tid >> 5;
    const int lane = tid & 31;
    const int m0 = blockIdx.y * 128;
    const int n0 = blockIdx.x * 128;

    if (tid < 128) {
        ((float*)(xsm + XS_BIAS))[tid] = bih[n0 + tid] + bhh[n0 + tid];
    }

    const int prow = tid >> 1;
    const int pseg0 = (tid & 1) * 4;
    auto load_chunk = [&](int kb, int buf) {
        uint32_t base = sb + (uint32_t)buf * XBUF;
        const __half* ax = g_xf + (size_t)(m0 + prow) * I_ + kb;
        const __half* wx = g_wf + (size_t)(n0 + prow) * I_ + kb;
        uint32_t ro = (uint32_t)prow * XPITCH;
#pragma unroll
        for (int s = 0; s < 4; s++) {
            int seg = pseg0 + s;
            uint32_t so = ro + (uint32_t)seg * 16;
            cp_async16(base + XSA + so, ax + seg * 8);
            cp_async16(base + XSW + so, wx + seg * 8);
        }
    };

    const int wm = wid & 3;
    const int wn = wid >> 2;
    const uint32_t a_row  = (uint32_t)(wm * 32 + (lane & 15));
    const uint32_t a_kofs = (uint32_t)((lane >> 4) * 8);
    const uint32_t b_col  = (uint32_t)(wn * 64 + ((lane >> 4) << 3) + (lane & 7));
    const uint32_t b_kofs = (uint32_t)(((lane >> 3) & 1) * 8);

    float acc[2][8][4];
#pragma unroll
    for (int i = 0; i < 2; i++)
#pragma unroll
        for (int j = 0; j < 8; j++)
#pragma unroll
            for (int k = 0; k < 4; k++) acc[i][j][k] = 0.f;

    load_chunk(0, 0);
    cp_commit();

    for (int ch = 0; ch < 16; ch++) {
        if (ch < 15) {
            load_chunk((ch + 1) * 64, (ch + 1) & 1);
            cp_commit();
            cp_wait<1>();
        } else {
            cp_wait<0>();
        }
        __syncthreads();

        uint32_t bufb = sb + (uint32_t)(ch & 1) * XBUF;
#pragma unroll
        for (int ks = 0; ks < 4; ks++) {
            unsigned a0r[4], a1r[4];
            uint32_t ak = (uint32_t)(ks * 16) + a_kofs;
            uint32_t a0 = bufb + XSA + a_row * XPITCH + ak * 2;
            uint32_t a1 = a0 + 16u * XPITCH;
            ldsm_x4(a0r, a0);
            ldsm_x4(a1r, a1);

#pragma unroll
            for (int ng = 0; ng < 4; ng++) {
                unsigned br[4];
                uint32_t bk = (uint32_t)(ks * 16) + b_kofs;
                uint32_t ba = bufb + XSW + (b_col + ng * 16) * XPITCH + bk * 2;
                ldsm_x4(br, ba);

                mma16816h(acc[0][ng * 2 + 0], a0r, br);
                mma16816h(acc[0][ng * 2 + 1], a0r, br + 2);
                mma16816h(acc[1][ng * 2 + 0], a1r, br);
                mma16816h(acc[1][ng * 2 + 1], a1r, br + 2);
            }
        }
        __syncthreads();
    }

    const float* bias = (const float*)(xsm + XS_BIAS);
    const int gid = lane >> 2;
    const int tig = lane & 3;
#pragma unroll
    for (int mi = 0; mi < 2; mi++) {
        int r0 = m0 + wm * 32 + mi * 16 + gid;
#pragma unroll
        for (int f = 0; f < 8; f++) {
            int cl = wn * 64 + f * 8 + tig * 2;
            float b0 = bias[cl], b1 = bias[cl + 1];
            float* p0 = g_xpre + (size_t)r0 * G4 + n0 + cl;
            *(float2*)p0 = make_float2(acc[mi][f][0] + b0, acc[mi][f][1] + b1);
            float* p1 = p0 + (size_t)8 * G4;
            *(float2*)p1 = make_float2(acc[mi][f][2] + b0, acc[mi][f][3] + b1);
        }
    }
}

// ---------------------------------------------------------------------------
// Phase 2: persistent warp-MMA scan — fp16, half-K double buffer.
// (byte-identical to the passing R15 kernel)
// ---------------------------------------------------------------------------
#define W_PITCH_B 2064                 // 1024 fp16 + 16 pad
#define A_PITCH_B 1040                 // 512 fp16 + 16 pad (=16 mod 128)
#define SM_W    0
#define SM_A0   (SM_W + 32 * W_PITCH_B)             // 66048
#define A_BUF   (64 * A_PITCH_B)                    // 66560
#define SM_PS   (SM_A0 + 2 * A_BUF)                 // 199168
#define PS_PITCH 68
#define SMEM_NEED (SM_PS + 32 * PS_PITCH * 4)       // 207872
#define SMEM_REQ  (SMEM_NEED + 1024)

__device__ __forceinline__ void grid_barrier(unsigned target) {
    __syncthreads();
    if (threadIdx.x == 0) {
        __threadfence();
        unsigned prev = atomicAdd(&g_arrive, 1u);
        if (prev == NBLK - 1) {
            atomicExch(&g_arrive, 0u);
            __threadfence();
            atomicAdd(&g_gen, 1u);
        } else {
            while (ld_acq(&g_gen) < target) { __nanosleep(32); }
        }
    }
    __syncthreads();
}

__global__ __launch_bounds__(NTHR, 1) void lstm_scan(
    const float* __restrict__ Whh,
    const float* __restrict__ c0,
    float* __restrict__ out)
{
    extern __shared__ char raw[];
    char* sm = (char*)(((uintptr_t)raw + 1023) & ~(uintptr_t)1023);
    const uint32_t sb = smem_u32(sm);

    const int tid  = threadIdx.x;
    const int wid  = tid >> 5;
    const int lane = tid & 31;
    const int j0   = blockIdx.x * 8;

    // --- preload W slice as fp16: row n (0..31) = gate col ---------------
    for (int it = 0; it < 128; it++) {
        int e = it * 256 + tid;          // 32768 elements
        int n = e >> 10;
        int k = e & 1023;
        int wrow = (n >> 3) * H_ + j0 + (n & 7);
        float w = __ldg(Whh + (size_t)wrow * H_ + k);
        *(__half*)(sm + SM_W + n * W_PITCH_B + k * 2) = __float2half(w);
    }

    // --- c0 into registers: thread owns (b = tid>>2, j = (tid&3)*2 + q) --
    const int cb = tid >> 2;
    const int cj = (tid & 3) * 2;
    float creg[2];
    creg[0] = c0[cb * H_ + j0 + cj];
    creg[1] = c0[cb * H_ + j0 + cj + 1];
    __syncthreads();

    // --- MMA thread mapping (verified lane maps) --------------------------
    const int wb = wid & 3;              // batch group (16 rows)
    const int wc = wid >> 2;             // col group (16 cols)
    const int gid = lane >> 2;           // 0..7
    const int tig = lane & 3;            // 0..3

    const uint32_t a_row  = (uint32_t)(wb * 16 + (lane & 15));
    const uint32_t a_kofs = (uint32_t)((lane >> 4) * 8);
    const uint32_t b_row  = (uint32_t)(wc * 16 + ((lane >> 4) << 3) + (lane & 7));
    const uint32_t b_kofs = (uint32_t)(((lane >> 3) & 1) * 8);

    for (int t = 0; t < T_; t++) {
        // x_pre prefetch into registers (no h dependency -> before barrier)
        const float* xp = g_xpre + ((size_t)t * B_ + cb) * G4 + j0 + cj;
        float2 xr0 = __ldcs((const float2*)(xp));
        float2 xr1 = __ldcs((const float2*)(xp + H_));
        float2 xr2 = __ldcs((const float2*)(xp + 2 * H_));
        float2 xr3 = __ldcs((const float2*)(xp + 3 * H_));

        grid_barrier((unsigned)(t + 1));

        const __half* hsrc = g_hf[t & 1];

        float acc0[4] = {0.f, 0.f, 0.f, 0.f};
        float acc1[4] = {0.f, 0.f, 0.f, 0.f};

        // issue BOTH half-K buffers up front (one commit group per half)
#pragma unroll
        for (int half = 0; half < 2; half++) {
            uint32_t base = sb + SM_A0 + (uint32_t)half * A_BUF;
            const __half* src = hsrc + half * 512;
#pragma unroll
            for (int i = 0; i < 16; i++) {
                int piece = i * 256 + tid;       // 0..4095
                int row = piece >> 6;            // 0..63
                int seg = piece & 63;            // 16B piece within 1024B row
                cp_async16(base + (uint32_t)(row * A_PITCH_B + seg * 16),
                           src + (size_t)row * H_ + seg * 8);
            }
            cp_commit();
        }

#pragma unroll
        for (int half = 0; half < 2; half++) {
            if (half == 0) cp_wait<1>(); else cp_wait<0>();
            __syncthreads();

            uint32_t abase = sb + SM_A0 + (uint32_t)half * A_BUF;
            uint32_t wbase = sb + SM_W + (uint32_t)half * 1024u;  // 512 fp16
#pragma unroll 8
            for (int ks = 0; ks < 32; ks++) {
                unsigned ah[4], bh[4];
                ldsm_x4(ah, abase + a_row * A_PITCH_B
                            + (uint32_t)ks * 32 + a_kofs * 2);
                ldsm_x4(bh, wbase + b_row * W_PITCH_B
                            + (uint32_t)ks * 32 + b_kofs * 2);
                mma16816h(acc0, ah, bh);
                mma16816h(acc1, ah, bh + 2);
            }
        }
        __syncthreads();

        // --- exchange: ps[col][batch] ------------------------------------
        float* ps = (float*)(sm + SM_PS);
        {
            int c0i = wc * 16 + tig * 2;
            int r0 = wb * 16 + gid;
            ps[(c0i + 0) * PS_PITCH + r0]     = acc0[0];
            ps[(c0i + 1) * PS_PITCH + r0]     = acc0[1];
            ps[(c0i + 0) * PS_PITCH + r0 + 8] = acc0[2];
            ps[(c0i + 1) * PS_PITCH + r0 + 8] = acc0[3];
            int c1i = c0i + 8;
            ps[(c1i + 0) * PS_PITCH + r0]     = acc1[0];
            ps[(c1i + 1) * PS_PITCH + r0]     = acc1[1];
            ps[(c1i + 0) * PS_PITCH + r0 + 8] = acc1[2];
            ps[(c1i + 1) * PS_PITCH + r0 + 8] = acc1[3];
        }
        __syncthreads();

        // --- gate combine: thread owns (cb, cj), (cb, cj+1) --------------
        float ht2[2];
#pragma unroll
        for (int q = 0; q < 2; q++) {
            int j = cj + q;
            float xi = q ? xr0.y : xr0.x;
            float xf = q ? xr1.y : xr1.x;
            float xo = q ? xr2.y : xr2.x;
            float xg = q ? xr3.y : xr3.x;
            float pi = ps[j * PS_PITCH + cb]        + xi;
            float pf = ps[(8 + j) * PS_PITCH + cb]  + xf;
            float po = ps[(16 + j) * PS_PITCH + cb] + xo;
            float pg = ps[(24 + j) * PS_PITCH + cb] + xg;

            float iv = 1.f / (1.f + expf(-pi));
            float fv = 1.f / (1.f + expf(-pf));
            float ov = 1.f / (1.f + expf(-po));
            float gv = tanhf(pg);

            float ct = fv * creg[q] + iv * gv;
            float hv = ov * tanhf(ct);
            creg[q] = ct;
            ht2[q] = hv;
        }

        // output (fp32, streaming) + next-h (fp16) stores
        __stcs((float2*)(out + ((size_t)t * B_ + cb) * H_ + j0 + cj),
               make_float2(ht2[0], ht2[1]));

        __half2 hp = __floats2half2_rn(ht2[0], ht2[1]);
        int hoff = cb * H_ + j0 + cj;
        __stcg((unsigned*)(g_hf[(t + 1) & 1] + hoff), *(unsigned*)&hp);

        if (t == T_ - 1) {
            *(float2*)(out + (size_t)T_ * B_ * H_ + hoff) =
                make_float2(ht2[0], ht2[1]);
            *(float2*)(out + (size_t)T_ * B_ * H_ + B_ * H_ + hoff) =
                make_float2(creg[0], creg[1]);
        }
        // release of h stores: next grid_barrier (sync + fence + atomic)
    }
}

// ---------------------------------------------------------------------------
extern "C" void kernel_launch(void* const* d_in, const int* in_sizes, int n_in,
                              void* d_out, int out_size) {
    const float* input = (const float*)d_in[0];   // [T,B,I]
    const float* h0    = (const float*)d_in[1];   // [1,B,H]
    const float* c0    = (const float*)d_in[2];   // [1,B,H]
    const float* W_ih  = (const float*)d_in[3];   // [4H,I]
    const float* b_ih  = (const float*)d_in[4];   // [4H]
    const float* W_hh  = (const float*)d_in[5];   // [4H,H]
    const float* b_hh  = (const float*)d_in[6];   // [4H]
    float* out = (float*)d_out;

    static int smem_set = 0;
    if (!smem_set) {
        cudaFuncSetAttribute(lstm_scan,
                             cudaFuncAttributeMaxDynamicSharedMemorySize,
                             SMEM_REQ);
        cudaFuncSetAttribute(hmma_xpre,
                             cudaFuncAttributeMaxDynamicSharedMemorySize,
                             XSMEM_REQ);
        smem_set = 1;
    }

    reset_barrier<<<1, 1>>>();
    init_state<<<(B_ * H_ + 255) / 256, 256>>>(h0);

    __half *xf, *wf;
    cudaGetSymbolAddress((void**)&xf, g_xf);
    cudaGetSymbolAddress((void**)&wf, g_wf);

    cvt_half<<<2048, 256>>>(input, xf, M_ * I_ / 4);
    cvt_half<<<1024, 256>>>(W_ih, wf, G4 * I_ / 4);

    hmma_xpre<<<dim3(G4 / 128, M_ / 128), 256, XSMEM_REQ>>>(b_ih, b_hh);
    lstm_scan<<<NBLK, NTHR, SMEM_REQ>>>(W_hh, c0, out);
}